// round 1
// baseline (speedup 1.0000x reference)
#include <cuda_runtime.h>
#include <math.h>

#define D_MODEL     256
#define EXPERT_DIM  512
#define NUM_EXPERTS 8
#define T_TOKENS    4096
#define TILE_T      32
#define MAX_TILES   (T_TOKENS / TILE_T)   // 128
#define CHUNK       64
#define NCHUNK      (EXPERT_DIM / CHUNK)  // 8

// ---- device scratch (no allocations allowed) ----
__device__ int   g_cnt[NUM_EXPERTS];
__device__ int   g_tok [NUM_EXPERTS][T_TOKENS];
__device__ float g_wt  [NUM_EXPERTS][T_TOKENS];
__device__ int   g_slot[NUM_EXPERTS][T_TOKENS];
__device__ float g_scratch[2][T_TOKENS][D_MODEL];   // 8 MB

// ---------------------------------------------------------------------------
__global__ void zero_kernel() {
    if (threadIdx.x < NUM_EXPERTS) g_cnt[threadIdx.x] = 0;
}

// ---------------------------------------------------------------------------
// One warp per token: gate logits, top-2, softmax, append to expert lists.
__global__ void route_kernel(const float* __restrict__ x,
                             const float* __restrict__ Wg,
                             const float* __restrict__ bg,
                             const float* __restrict__ bias) {
    int warp = (blockIdx.x * blockDim.x + threadIdx.x) >> 5;
    int lane = threadIdx.x & 31;
    if (warp >= T_TOKENS) return;
    int t = warp;

    const float* xr = x + (size_t)t * D_MODEL;
    float acc[NUM_EXPERTS];
#pragma unroll
    for (int e = 0; e < NUM_EXPERTS; e++) acc[e] = 0.f;

#pragma unroll
    for (int j = 0; j < D_MODEL / 32; j++) {
        int k = lane + j * 32;
        float xv = xr[k];
        const float4* wrow = (const float4*)(Wg + (size_t)k * NUM_EXPERTS);
        float4 w0 = wrow[0], w1 = wrow[1];
        acc[0] += xv * w0.x; acc[1] += xv * w0.y;
        acc[2] += xv * w0.z; acc[3] += xv * w0.w;
        acc[4] += xv * w1.x; acc[5] += xv * w1.y;
        acc[6] += xv * w1.z; acc[7] += xv * w1.w;
    }
#pragma unroll
    for (int e = 0; e < NUM_EXPERTS; e++) {
#pragma unroll
        for (int off = 16; off > 0; off >>= 1)
            acc[e] += __shfl_xor_sync(0xffffffffu, acc[e], off);
    }

    if (lane == 0) {
        float best = -INFINITY, second = -INFINITY;
        int b0 = 0, b1 = 0;
#pragma unroll
        for (int e = 0; e < NUM_EXPERTS; e++) {
            float v = acc[e] + bg[e] + bias[e];
            if (v > best)       { second = best; b1 = b0; best = v; b0 = e; }
            else if (v > second){ second = v; b1 = e; }
        }
        float e1  = expf(second - best);
        float inv = 1.f / (1.f + e1);
        float w0 = inv, w1 = e1 * inv;

        int p0 = atomicAdd(&g_cnt[b0], 1);
        g_tok[b0][p0] = t; g_wt[b0][p0] = w0; g_slot[b0][p0] = 0;
        int p1 = atomicAdd(&g_cnt[b1], 1);
        g_tok[b1][p1] = t; g_wt[b1][p1] = w1; g_slot[b1][p1] = 1;
    }
}

// ---------------------------------------------------------------------------
// One block = (expert e, tile of up to 32 of its tokens).
// Fused: h = relu(X@W1 + b1) in 64-col chunks; acc += h_chunk @ W2_chunk.
// Epilogue: scratch[slot][t] = w * (acc + b2).
__global__ void __launch_bounds__(256, 2)
expert_kernel(const float* __restrict__ x,
              const float* __restrict__ W1,
              const float* __restrict__ b1,
              const float* __restrict__ W2,
              const float* __restrict__ b2) {
    __shared__ float Xs[TILE_T][D_MODEL];   // 32 KB
    __shared__ float Hs[TILE_T][CHUNK];     // 8 KB
    __shared__ int   s_tok[TILE_T];
    __shared__ float s_wt[TILE_T];
    __shared__ int   s_slot[TILE_T];

    int e    = blockIdx.x >> 7;               // / MAX_TILES
    int tile = blockIdx.x & (MAX_TILES - 1);
    int n = g_cnt[e];
    int start = tile * TILE_T;
    if (start >= n) return;
    int m = min(TILE_T, n - start);
    int tid = threadIdx.x;

    if (tid < TILE_T) {
        if (tid < m) {
            s_tok[tid]  = g_tok [e][start + tid];
            s_wt[tid]   = g_wt  [e][start + tid];
            s_slot[tid] = g_slot[e][start + tid];
        } else {
            s_tok[tid] = 0; s_wt[tid] = 0.f; s_slot[tid] = 0;
        }
    }
    __syncthreads();

    // gather X tile: 32 rows x 64 float4
#pragma unroll
    for (int j = 0; j < 8; j++) {
        int idx = tid + j * 256;      // 0..2047
        int row = idx >> 6;
        int q   = idx & 63;
        float4 v = make_float4(0.f, 0.f, 0.f, 0.f);
        if (row < m)
            v = ((const float4*)(x + (size_t)s_tok[row] * D_MODEL))[q];
        *((float4*)&Xs[row][q * 4]) = v;
    }
    __syncthreads();

    const float* W1e = W1 + (size_t)e * D_MODEL * EXPERT_DIM;
    const float* W2e = W2 + (size_t)e * EXPERT_DIM * D_MODEL;
    const float* b1e = b1 + e * EXPERT_DIM;
    const float* b2e = b2 + e * D_MODEL;

    int tg = tid >> 5;      // token group (0..7): tokens tg*4 .. tg*4+3
    int lg = tid & 31;      // lane group

    float acc2[4][8];
#pragma unroll
    for (int i = 0; i < 4; i++)
#pragma unroll
        for (int j = 0; j < 8; j++) acc2[i][j] = 0.f;

    for (int c = 0; c < NCHUNK; c++) {
        // ---- GEMM1: h[32][CHUNK], each thread 4 tokens x 2 h-cols ----
        float a1[4][2];
#pragma unroll
        for (int i = 0; i < 4; i++) { a1[i][0] = 0.f; a1[i][1] = 0.f; }
        int h0 = c * CHUNK + lg * 2;
        const float* w1p = W1e + h0;
#pragma unroll 4
        for (int k = 0; k < D_MODEL; k++) {
            float2 w = *((const float2*)(w1p + (size_t)k * EXPERT_DIM));
            float x0 = Xs[tg * 4 + 0][k];
            float x1 = Xs[tg * 4 + 1][k];
            float x2 = Xs[tg * 4 + 2][k];
            float x3 = Xs[tg * 4 + 3][k];
            a1[0][0] += x0 * w.x; a1[0][1] += x0 * w.y;
            a1[1][0] += x1 * w.x; a1[1][1] += x1 * w.y;
            a1[2][0] += x2 * w.x; a1[2][1] += x2 * w.y;
            a1[3][0] += x3 * w.x; a1[3][1] += x3 * w.y;
        }
        float bb0 = b1e[h0], bb1 = b1e[h0 + 1];
        __syncthreads();   // previous chunk's Hs readers done
#pragma unroll
        for (int i = 0; i < 4; i++) {
            float v0 = fmaxf(a1[i][0] + bb0, 0.f);
            float v1 = fmaxf(a1[i][1] + bb1, 0.f);
            *((float2*)&Hs[tg * 4 + i][lg * 2]) = make_float2(v0, v1);
        }
        __syncthreads();

        // ---- GEMM2: acc2 += Hs @ W2_chunk, each thread 4 tokens x 8 d-cols
        const float* w2p = W2e + (size_t)(c * CHUNK) * D_MODEL + lg * 8;
#pragma unroll 2
        for (int hk = 0; hk < CHUNK; hk++) {
            float4 wa = *((const float4*)(w2p + (size_t)hk * D_MODEL));
            float4 wb = *((const float4*)(w2p + (size_t)hk * D_MODEL + 4));
            float wv[8] = { wa.x, wa.y, wa.z, wa.w, wb.x, wb.y, wb.z, wb.w };
            float hv[4];
#pragma unroll
            for (int i = 0; i < 4; i++) hv[i] = Hs[tg * 4 + i][hk];
#pragma unroll
            for (int i = 0; i < 4; i++)
#pragma unroll
                for (int j = 0; j < 8; j++) acc2[i][j] += hv[i] * wv[j];
        }
    }

    // ---- epilogue: scratch[slot][t][lg*8 .. +7] = w * (acc + b2) ----
    float bb[8];
#pragma unroll
    for (int j = 0; j < 8; j++) bb[j] = b2e[lg * 8 + j];
#pragma unroll
    for (int i = 0; i < 4; i++) {
        int r = tg * 4 + i;
        if (r < m) {
            float wgt = s_wt[r];
            float* op = &g_scratch[s_slot[r]][s_tok[r]][lg * 8];
            float4 o0, o1;
            o0.x = wgt * (acc2[i][0] + bb[0]);
            o0.y = wgt * (acc2[i][1] + bb[1]);
            o0.z = wgt * (acc2[i][2] + bb[2]);
            o0.w = wgt * (acc2[i][3] + bb[3]);
            o1.x = wgt * (acc2[i][4] + bb[4]);
            o1.y = wgt * (acc2[i][5] + bb[5]);
            o1.z = wgt * (acc2[i][6] + bb[6]);
            o1.w = wgt * (acc2[i][7] + bb[7]);
            ((float4*)op)[0] = o0;
            ((float4*)op)[1] = o1;
        }
    }
}

// ---------------------------------------------------------------------------
__global__ void combine_kernel(float* __restrict__ out) {
    int idx = blockIdx.x * blockDim.x + threadIdx.x;   // over T*D/4 float4s
    const float4* s0 = (const float4*)g_scratch[0];
    const float4* s1 = (const float4*)g_scratch[1];
    float4 a = s0[idx], b = s1[idx];
    float4 o;
    o.x = a.x + b.x; o.y = a.y + b.y; o.z = a.z + b.z; o.w = a.w + b.w;
    ((float4*)out)[idx] = o;
}

// ---------------------------------------------------------------------------
extern "C" void kernel_launch(void* const* d_in, const int* in_sizes, int n_in,
                              void* d_out, int out_size) {
    const float* x    = (const float*)d_in[0];
    const float* Wg   = (const float*)d_in[1];
    const float* bg   = (const float*)d_in[2];
    const float* bias = (const float*)d_in[3];
    const float* W1   = (const float*)d_in[4];
    const float* b1   = (const float*)d_in[5];
    const float* W2   = (const float*)d_in[6];
    const float* b2   = (const float*)d_in[7];
    float* out = (float*)d_out;

    zero_kernel<<<1, 32>>>();
    route_kernel<<<(T_TOKENS * 32) / 256, 256>>>(x, Wg, bg, bias);
    expert_kernel<<<NUM_EXPERTS * MAX_TILES, 256>>>(x, W1, b1, W2, b2);
    combine_kernel<<<(T_TOKENS * D_MODEL / 4) / 256, 256>>>(out);
}

// round 2
// speedup vs baseline: 1.6496x; 1.6496x over previous
#include <cuda_runtime.h>
#include <math.h>
#include <stdint.h>

#define D_MODEL     256
#define EXPERT_DIM  512
#define NUM_EXPERTS 8
#define T_TOKENS    4096
#define TILE_T      32
#define MAX_TILES   (T_TOKENS / TILE_T)   // 128

// ---- device scratch (no allocations allowed) ----
__device__ int   g_cnt[NUM_EXPERTS];
__device__ int   g_tok [NUM_EXPERTS][T_TOKENS];
__device__ float g_wt  [NUM_EXPERTS][T_TOKENS];
__device__ int   g_slot[NUM_EXPERTS][T_TOKENS];
__device__ float g_scratch[2][T_TOKENS][D_MODEL];                 // 8 MB
__device__ float g_W1c[NUM_EXPERTS * D_MODEL * EXPERT_DIM];       // 4 MB, tf32-rounded
__device__ float g_W2c[NUM_EXPERTS * EXPERT_DIM * D_MODEL];       // 4 MB, tf32-rounded

// ---------------------------------------------------------------------------
__device__ __forceinline__ float tf32r(float x) {
    uint32_t u;
    asm("cvt.rna.tf32.f32 %0, %1;" : "=r"(u) : "f"(x));
    return __uint_as_float(u);
}

__device__ __forceinline__ void mma_tf32(float c[4], const float a[4],
                                         float b0, float b1) {
    const uint32_t* A = reinterpret_cast<const uint32_t*>(a);
    uint32_t B0 = __float_as_uint(b0), B1 = __float_as_uint(b1);
    asm volatile(
        "mma.sync.aligned.m16n8k8.row.col.f32.tf32.tf32.f32 "
        "{%0,%1,%2,%3}, {%4,%5,%6,%7}, {%8,%9}, {%0,%1,%2,%3};\n"
        : "+f"(c[0]), "+f"(c[1]), "+f"(c[2]), "+f"(c[3])
        : "r"(A[0]), "r"(A[1]), "r"(A[2]), "r"(A[3]), "r"(B0), "r"(B1));
}

// ---------------------------------------------------------------------------
__global__ void zero_kernel() {
    if (threadIdx.x < NUM_EXPERTS) g_cnt[threadIdx.x] = 0;
}

// Pre-round all expert weights to tf32 (rna) once per launch.
__global__ void convert_w_kernel(const float* __restrict__ W1,
                                 const float* __restrict__ W2) {
    int j = blockIdx.x * blockDim.x + threadIdx.x;
    const int N4 = NUM_EXPERTS * D_MODEL * EXPERT_DIM / 4;   // 262144 float4s
    float4 v; float4* dst;
    if (j < N4) { v = ((const float4*)W1)[j]; dst = (float4*)g_W1c + j; }
    else        { v = ((const float4*)W2)[j - N4]; dst = (float4*)g_W2c + (j - N4); }
    v.x = tf32r(v.x); v.y = tf32r(v.y); v.z = tf32r(v.z); v.w = tf32r(v.w);
    *dst = v;
}

// ---------------------------------------------------------------------------
// One warp per token: gate logits, top-2, softmax, append to expert lists.
__global__ void route_kernel(const float* __restrict__ x,
                             const float* __restrict__ Wg,
                             const float* __restrict__ bg,
                             const float* __restrict__ bias) {
    int warp = (blockIdx.x * blockDim.x + threadIdx.x) >> 5;
    int lane = threadIdx.x & 31;
    if (warp >= T_TOKENS) return;
    int t = warp;

    const float* xr = x + (size_t)t * D_MODEL;
    float acc[NUM_EXPERTS];
#pragma unroll
    for (int e = 0; e < NUM_EXPERTS; e++) acc[e] = 0.f;

#pragma unroll
    for (int j = 0; j < D_MODEL / 32; j++) {
        int k = lane + j * 32;
        float xv = xr[k];
        const float4* wrow = (const float4*)(Wg + (size_t)k * NUM_EXPERTS);
        float4 w0 = wrow[0], w1 = wrow[1];
        acc[0] += xv * w0.x; acc[1] += xv * w0.y;
        acc[2] += xv * w0.z; acc[3] += xv * w0.w;
        acc[4] += xv * w1.x; acc[5] += xv * w1.y;
        acc[6] += xv * w1.z; acc[7] += xv * w1.w;
    }
#pragma unroll
    for (int e = 0; e < NUM_EXPERTS; e++) {
#pragma unroll
        for (int off = 16; off > 0; off >>= 1)
            acc[e] += __shfl_xor_sync(0xffffffffu, acc[e], off);
    }

    if (lane == 0) {
        float best = -INFINITY, second = -INFINITY;
        int b0 = 0, b1 = 0;
#pragma unroll
        for (int e = 0; e < NUM_EXPERTS; e++) {
            float v = acc[e] + bg[e] + bias[e];
            if (v > best)        { second = best; b1 = b0; best = v; b0 = e; }
            else if (v > second) { second = v; b1 = e; }
        }
        float e1  = expf(second - best);
        float inv = 1.f / (1.f + e1);

        int p0 = atomicAdd(&g_cnt[b0], 1);
        g_tok[b0][p0] = t; g_wt[b0][p0] = inv;      g_slot[b0][p0] = 0;
        int p1 = atomicAdd(&g_cnt[b1], 1);
        g_tok[b1][p1] = t; g_wt[b1][p1] = e1 * inv; g_slot[b1][p1] = 1;
    }
}

// ---------------------------------------------------------------------------
// One block = (expert, tile of up to 32 tokens). 128 threads = 4 warps.
// tf32 mma.sync path. Warp wn owns an n-slice; both m-halves per warp.
// GEMM1 chunk: H[32, 64] = relu(Xs @ W1[:, c*64:+64] + b1), tf32-rounded -> Hs
// GEMM2 chunk: acc += Hs @ W2[c*64:+64, :]
__global__ void __launch_bounds__(128)
expert_kernel(const float* __restrict__ x,
              const float* __restrict__ b1,
              const float* __restrict__ b2) {
    __shared__ float Xs[TILE_T][260];   // pad 4: A-frag LDS bank-free (4r+t)
    __shared__ float Hs[TILE_T][68];    // pad 4: same
    __shared__ int   s_tok[TILE_T];
    __shared__ float s_wt[TILE_T];
    __shared__ int   s_slot[TILE_T];

    int e    = blockIdx.x >> 7;          // / MAX_TILES
    int tile = blockIdx.x & (MAX_TILES - 1);
    int n_e  = g_cnt[e];
    int start = tile * TILE_T;
    if (start >= n_e) return;
    int m = min(TILE_T, n_e - start);
    int tid = threadIdx.x;

    if (tid < TILE_T) {
        if (tid < m) {
            s_tok[tid]  = g_tok [e][start + tid];
            s_wt[tid]   = g_wt  [e][start + tid];
            s_slot[tid] = g_slot[e][start + tid];
        } else {
            s_tok[tid] = 0; s_wt[tid] = 0.f; s_slot[tid] = 0;
        }
    }
    __syncthreads();

    // gather X tile (tf32-rounded): 32 rows x 64 float4 = 2048, 16 iters
#pragma unroll
    for (int it = 0; it < 16; it++) {
        int idx = tid + it * 128;
        int row = idx >> 6, q = idx & 63;
        float4 v = make_float4(0.f, 0.f, 0.f, 0.f);
        if (row < m)
            v = ((const float4*)(x + (size_t)s_tok[row] * D_MODEL))[q];
        v.x = tf32r(v.x); v.y = tf32r(v.y); v.z = tf32r(v.z); v.w = tf32r(v.w);
        *((float4*)&Xs[row][q * 4]) = v;
    }
    __syncthreads();

    const float* W1p = g_W1c + (size_t)e * D_MODEL * EXPERT_DIM;
    const float* W2p = g_W2c + (size_t)e * EXPERT_DIM * D_MODEL;
    const float* b1e = b1 + e * EXPERT_DIM;
    const float* b2e = b2 + e * D_MODEL;

    int wn   = tid >> 5;        // warp 0..3 -> n-slice owner
    int lane = tid & 31;
    int g = lane >> 2, t = lane & 3;

    float acc2[2][8][4];
#pragma unroll
    for (int mi = 0; mi < 2; mi++)
#pragma unroll
        for (int f = 0; f < 8; f++)
#pragma unroll
            for (int r = 0; r < 4; r++) acc2[mi][f][r] = 0.f;

    for (int c = 0; c < 8; c++) {
        // ---------------- GEMM1: warp computes m32 x n16 of H chunk --------
        float c1[2][2][4];
#pragma unroll
        for (int mi = 0; mi < 2; mi++)
#pragma unroll
            for (int f = 0; f < 2; f++)
#pragma unroll
                for (int r = 0; r < 4; r++) c1[mi][f][r] = 0.f;

        const float* w1base = W1p + c * 64 + wn * 16;
#pragma unroll 4
        for (int ks = 0; ks < 32; ks++) {
            int k0 = ks * 8;
            float a[2][4];
#pragma unroll
            for (int mi = 0; mi < 2; mi++) {
                int r = 16 * mi + g;
                a[mi][0] = Xs[r][k0 + t];
                a[mi][1] = Xs[r + 8][k0 + t];
                a[mi][2] = Xs[r][k0 + t + 4];
                a[mi][3] = Xs[r + 8][k0 + t + 4];
            }
#pragma unroll
            for (int f = 0; f < 2; f++) {
                const float* bp = w1base + (size_t)(k0 + t) * EXPERT_DIM + 8 * f + g;
                float b0 = bp[0];
                float bv = bp[4 * EXPERT_DIM];
                mma_tf32(c1[0][f], a[0], b0, bv);
                mma_tf32(c1[1][f], a[1], b0, bv);
            }
        }

        __syncthreads();   // previous chunk's Hs readers done
        // bias + relu + tf32 round -> Hs
#pragma unroll
        for (int mi = 0; mi < 2; mi++) {
#pragma unroll
            for (int f = 0; f < 2; f++) {
                int lc = wn * 16 + 8 * f + 2 * t;
                float bv0 = b1e[c * 64 + lc];
                float bv1 = b1e[c * 64 + lc + 1];
                int r = 16 * mi + g;
                float2 lo, hi;
                lo.x = tf32r(fmaxf(c1[mi][f][0] + bv0, 0.f));
                lo.y = tf32r(fmaxf(c1[mi][f][1] + bv1, 0.f));
                hi.x = tf32r(fmaxf(c1[mi][f][2] + bv0, 0.f));
                hi.y = tf32r(fmaxf(c1[mi][f][3] + bv1, 0.f));
                *((float2*)&Hs[r][lc])     = lo;
                *((float2*)&Hs[r + 8][lc]) = hi;
            }
        }
        __syncthreads();

        // ---------------- GEMM2: warp computes m32 x n64, K=64 ------------
        const float* w2base = W2p + (size_t)(c * 64) * D_MODEL + wn * 64;
#pragma unroll
        for (int ks = 0; ks < 8; ks++) {
            int k0 = ks * 8;
            float a[2][4];
#pragma unroll
            for (int mi = 0; mi < 2; mi++) {
                int r = 16 * mi + g;
                a[mi][0] = Hs[r][k0 + t];
                a[mi][1] = Hs[r + 8][k0 + t];
                a[mi][2] = Hs[r][k0 + t + 4];
                a[mi][3] = Hs[r + 8][k0 + t + 4];
            }
#pragma unroll
            for (int f = 0; f < 8; f++) {
                const float* bp = w2base + (size_t)(k0 + t) * D_MODEL + 8 * f + g;
                float b0 = bp[0];
                float bv = bp[4 * D_MODEL];
                mma_tf32(acc2[0][f], a[0], b0, bv);
                mma_tf32(acc2[1][f], a[1], b0, bv);
            }
        }
    }

    // ---- epilogue: scratch[slot][tok][col] = w * (acc + b2) ----
#pragma unroll
    for (int mi = 0; mi < 2; mi++) {
#pragma unroll
        for (int hrow = 0; hrow < 2; hrow++) {
            int r = 16 * mi + g + 8 * hrow;
            if (r < m) {
                float wgt = s_wt[r];
                float* op = &g_scratch[s_slot[r]][s_tok[r]][0];
#pragma unroll
                for (int f = 0; f < 8; f++) {
                    int col = wn * 64 + 8 * f + 2 * t;
                    float v0 = acc2[mi][f][2 * hrow + 0];
                    float v1 = acc2[mi][f][2 * hrow + 1];
                    float2 o;
                    o.x = wgt * (v0 + b2e[col]);
                    o.y = wgt * (v1 + b2e[col + 1]);
                    *((float2*)(op + col)) = o;
                }
            }
        }
    }
}

// ---------------------------------------------------------------------------
__global__ void combine_kernel(float* __restrict__ out) {
    int idx = blockIdx.x * blockDim.x + threadIdx.x;   // over T*D/4 float4s
    const float4* s0 = (const float4*)g_scratch[0];
    const float4* s1 = (const float4*)g_scratch[1];
    float4 a = s0[idx], b = s1[idx];
    float4 o;
    o.x = a.x + b.x; o.y = a.y + b.y; o.z = a.z + b.z; o.w = a.w + b.w;
    ((float4*)out)[idx] = o;
}

// ---------------------------------------------------------------------------
extern "C" void kernel_launch(void* const* d_in, const int* in_sizes, int n_in,
                              void* d_out, int out_size) {
    const float* x    = (const float*)d_in[0];
    const float* Wg   = (const float*)d_in[1];
    const float* bg   = (const float*)d_in[2];
    const float* bias = (const float*)d_in[3];
    const float* W1   = (const float*)d_in[4];
    const float* b1   = (const float*)d_in[5];
    const float* W2   = (const float*)d_in[6];
    const float* b2   = (const float*)d_in[7];
    float* out = (float*)d_out;

    zero_kernel<<<1, 32>>>();
    convert_w_kernel<<<2048, 256>>>(W1, W2);
    route_kernel<<<(T_TOKENS * 32) / 256, 256>>>(x, Wg, bg, bias);
    expert_kernel<<<NUM_EXPERTS * MAX_TILES, 128>>>(x, b1, b2);
    combine_kernel<<<(T_TOKENS * D_MODEL / 4) / 256, 256>>>(out);
}

// round 3
// speedup vs baseline: 1.8786x; 1.1389x over previous
#include <cuda_runtime.h>
#include <math.h>
#include <stdint.h>

#define D_MODEL     256
#define EXPERT_DIM  512
#define NUM_EXPERTS 8
#define T_TOKENS    4096
#define TILE_T      32
#define MAX_TILES   (T_TOKENS / TILE_T)   // 128

#define XS_STRIDE   260
#define HS_STRIDE   68
#define W1S_STRIDE  72
#define W2S_STRIDE  264
#define STAGE_FLOATS 4224   // max(32*72=2304, 16*264=4224)
#define SMEM_FLOATS  (32*XS_STRIDE + 32*HS_STRIDE + 2*STAGE_FLOATS + 96)
#define SMEM_BYTES   (SMEM_FLOATS * 4)

// ---- device scratch (no allocations allowed) ----
__device__ int   g_cnt[NUM_EXPERTS];
__device__ int   g_tok [NUM_EXPERTS][T_TOKENS];
__device__ float g_wt  [NUM_EXPERTS][T_TOKENS];
__device__ int   g_slot[NUM_EXPERTS][T_TOKENS];
__device__ float g_scratch[2][T_TOKENS][D_MODEL];                 // 8 MB
__device__ float g_W1c[NUM_EXPERTS * D_MODEL * EXPERT_DIM];       // 4 MB tf32-rounded
__device__ float g_W2c[NUM_EXPERTS * EXPERT_DIM * D_MODEL];       // 4 MB tf32-rounded

// ---------------------------------------------------------------------------
__device__ __forceinline__ float tf32r(float x) {
    uint32_t u;
    asm("cvt.rna.tf32.f32 %0, %1;" : "=r"(u) : "f"(x));
    return __uint_as_float(u);
}

__device__ __forceinline__ void mma_tf32(float c[4], const float a[4],
                                         float b0, float b1) {
    const uint32_t* A = reinterpret_cast<const uint32_t*>(a);
    uint32_t B0 = __float_as_uint(b0), B1 = __float_as_uint(b1);
    asm volatile(
        "mma.sync.aligned.m16n8k8.row.col.f32.tf32.tf32.f32 "
        "{%0,%1,%2,%3}, {%4,%5,%6,%7}, {%8,%9}, {%0,%1,%2,%3};\n"
        : "+f"(c[0]), "+f"(c[1]), "+f"(c[2]), "+f"(c[3])
        : "r"(A[0]), "r"(A[1]), "r"(A[2]), "r"(A[3]), "r"(B0), "r"(B1));
}

__device__ __forceinline__ void cp16(uint32_t dst, const float* src) {
    asm volatile("cp.async.ca.shared.global [%0], [%1], 16;" :: "r"(dst), "l"(src));
}
__device__ __forceinline__ void cp_commit() {
    asm volatile("cp.async.commit_group;");
}
__device__ __forceinline__ void cp_wait1() {
    asm volatile("cp.async.wait_group 1;");
}

// ---------------------------------------------------------------------------
__global__ void zero_kernel() {
    if (threadIdx.x < NUM_EXPERTS) g_cnt[threadIdx.x] = 0;
}

// Pre-round all expert weights to tf32 (rna) once per launch.
__global__ void convert_w_kernel(const float* __restrict__ W1,
                                 const float* __restrict__ W2) {
    int j = blockIdx.x * blockDim.x + threadIdx.x;
    const int N4 = NUM_EXPERTS * D_MODEL * EXPERT_DIM / 4;
    float4 v; float4* dst;
    if (j < N4) { v = ((const float4*)W1)[j]; dst = (float4*)g_W1c + j; }
    else        { v = ((const float4*)W2)[j - N4]; dst = (float4*)g_W2c + (j - N4); }
    v.x = tf32r(v.x); v.y = tf32r(v.y); v.z = tf32r(v.z); v.w = tf32r(v.w);
    *dst = v;
}

// ---------------------------------------------------------------------------
__global__ void route_kernel(const float* __restrict__ x,
                             const float* __restrict__ Wg,
                             const float* __restrict__ bg,
                             const float* __restrict__ bias) {
    int warp = (blockIdx.x * blockDim.x + threadIdx.x) >> 5;
    int lane = threadIdx.x & 31;
    if (warp >= T_TOKENS) return;
    int t = warp;

    const float* xr = x + (size_t)t * D_MODEL;
    float acc[NUM_EXPERTS];
#pragma unroll
    for (int e = 0; e < NUM_EXPERTS; e++) acc[e] = 0.f;

#pragma unroll
    for (int j = 0; j < D_MODEL / 32; j++) {
        int k = lane + j * 32;
        float xv = xr[k];
        const float4* wrow = (const float4*)(Wg + (size_t)k * NUM_EXPERTS);
        float4 w0 = wrow[0], w1 = wrow[1];
        acc[0] += xv * w0.x; acc[1] += xv * w0.y;
        acc[2] += xv * w0.z; acc[3] += xv * w0.w;
        acc[4] += xv * w1.x; acc[5] += xv * w1.y;
        acc[6] += xv * w1.z; acc[7] += xv * w1.w;
    }
#pragma unroll
    for (int e = 0; e < NUM_EXPERTS; e++) {
#pragma unroll
        for (int off = 16; off > 0; off >>= 1)
            acc[e] += __shfl_xor_sync(0xffffffffu, acc[e], off);
    }

    if (lane == 0) {
        float best = -INFINITY, second = -INFINITY;
        int b0 = 0, b1 = 0;
#pragma unroll
        for (int e = 0; e < NUM_EXPERTS; e++) {
            float v = acc[e] + bg[e] + bias[e];
            if (v > best)        { second = best; b1 = b0; best = v; b0 = e; }
            else if (v > second) { second = v; b1 = e; }
        }
        float e1  = expf(second - best);
        float inv = 1.f / (1.f + e1);

        int p0 = atomicAdd(&g_cnt[b0], 1);
        g_tok[b0][p0] = t; g_wt[b0][p0] = inv;      g_slot[b0][p0] = 0;
        int p1 = atomicAdd(&g_cnt[b1], 1);
        g_tok[b1][p1] = t; g_wt[b1][p1] = e1 * inv; g_slot[b1][p1] = 1;
    }
}

// ---------------------------------------------------------------------------
// One block = (expert, up to 32 tokens). 256 threads = 8 warps (2m x 4n).
// Weights cp.async double-buffered through SMEM; tf32 mma.sync.
__global__ void __launch_bounds__(256, 3)
expert_kernel(const float* __restrict__ x,
              const float* __restrict__ b1,
              const float* __restrict__ b2) {
    extern __shared__ float sm[];
    float* Xs  = sm;                               // [32][260]
    float* Hs  = sm + 32 * XS_STRIDE;              // [32][68]
    float* Wst = Hs + 32 * HS_STRIDE;              // [2][4224]
    int*   s_tok  = (int*)(Wst + 2 * STAGE_FLOATS);
    float* s_wt   = (float*)(s_tok + 32);
    int*   s_slot = (int*)(s_wt + 32);

    int e    = blockIdx.x >> 7;
    int tile = blockIdx.x & (MAX_TILES - 1);
    int n_e  = g_cnt[e];
    int start = tile * TILE_T;
    if (start >= n_e) return;
    int m = min(TILE_T, n_e - start);
    int tid = threadIdx.x;

    const float* W1p = g_W1c + (size_t)e * D_MODEL * EXPERT_DIM;
    const float* W2p = g_W2c + (size_t)e * EXPERT_DIM * D_MODEL;
    const float* b1e = b1 + e * EXPERT_DIM;
    const float* b2e = b2 + e * D_MODEL;

    uint32_t wst_sa = (uint32_t)__cvta_generic_to_shared(Wst);

    // stage copy helpers (all 256 threads participate)
    // W1 stage: rows kb*32..+32 of K, cols c*64..+64  -> [32][72]
    // W2 stage: rows c*64+kb*16..+16, cols 0..256     -> [16][264]
    auto stage1 = [&](int buf, int c, int kb) {
#pragma unroll
        for (int i = 0; i < 2; i++) {
            int o = tid + 256 * i;                 // 512 float4
            int row = o >> 4, q = o & 15;
            uint32_t dst = wst_sa + (buf * STAGE_FLOATS + row * W1S_STRIDE + q * 4) * 4;
            cp16(dst, W1p + (size_t)(kb * 32 + row) * EXPERT_DIM + c * 64 + q * 4);
        }
    };
    auto stage2 = [&](int buf, int c, int kb) {
#pragma unroll
        for (int i = 0; i < 4; i++) {
            int o = tid + 256 * i;                 // 1024 float4
            int row = o >> 6, q = o & 63;
            uint32_t dst = wst_sa + (buf * STAGE_FLOATS + row * W2S_STRIDE + q * 4) * 4;
            cp16(dst, W2p + (size_t)(c * 64 + kb * 16 + row) * D_MODEL + q * 4);
        }
    };

    // kick off first weight stage immediately
    stage1(0, 0, 0);
    cp_commit();

    if (tid < TILE_T) {
        if (tid < m) {
            s_tok[tid]  = g_tok [e][start + tid];
            s_wt[tid]   = g_wt  [e][start + tid];
            s_slot[tid] = g_slot[e][start + tid];
        } else {
            s_tok[tid] = 0; s_wt[tid] = 0.f; s_slot[tid] = 0;
        }
    }
    __syncthreads();

    // gather X tile (tf32-rounded): 2048 float4, 8 iters
#pragma unroll
    for (int it = 0; it < 8; it++) {
        int idx = tid + it * 256;
        int row = idx >> 6, q = idx & 63;
        float4 v = make_float4(0.f, 0.f, 0.f, 0.f);
        if (row < m)
            v = ((const float4*)(x + (size_t)s_tok[row] * D_MODEL))[q];
        v.x = tf32r(v.x); v.y = tf32r(v.y); v.z = tf32r(v.z); v.w = tf32r(v.w);
        *((float4*)&Xs[row * XS_STRIDE + q * 4]) = v;
    }
    __syncthreads();

    int wid  = tid >> 5;
    int wm   = wid >> 2;        // 0..1  m-group (rows 16*wm .. +16)
    int wn   = wid & 3;         // 0..3  n-group
    int lane = tid & 31;
    int g = lane >> 2, t = lane & 3;
    int rA = 16 * wm + g;

    float acc2[8][4];
#pragma unroll
    for (int f = 0; f < 8; f++)
#pragma unroll
        for (int r = 0; r < 4; r++) acc2[f][r] = 0.f;

    int buf = 0;
    for (int c = 0; c < 8; c++) {
        // ================= GEMM1: H[32][64] chunk, K=256, 8 stages ========
        float c1[2][4];
#pragma unroll
        for (int f = 0; f < 2; f++)
#pragma unroll
            for (int r = 0; r < 4; r++) c1[f][r] = 0.f;

        for (int kb = 0; kb < 8; kb++) {
            if (kb < 7) stage1(buf ^ 1, c, kb + 1);
            else        stage2(buf ^ 1, c, 0);
            cp_commit();
            cp_wait1();
            __syncthreads();

            const float* Ws = Wst + buf * STAGE_FLOATS;
#pragma unroll
            for (int ks = 0; ks < 4; ks++) {
                int k0 = kb * 32 + ks * 8 + t;
                float a[4];
                a[0] = Xs[rA * XS_STRIDE + k0];
                a[1] = Xs[(rA + 8) * XS_STRIDE + k0];
                a[2] = Xs[rA * XS_STRIDE + k0 + 4];
                a[3] = Xs[(rA + 8) * XS_STRIDE + k0 + 4];
#pragma unroll
                for (int f = 0; f < 2; f++) {
                    int col = 16 * wn + 8 * f + g;
                    float b0 = Ws[(ks * 8 + t) * W1S_STRIDE + col];
                    float bv = Ws[(ks * 8 + t + 4) * W1S_STRIDE + col];
                    mma_tf32(c1[f], a, b0, bv);
                }
            }
            __syncthreads();
            buf ^= 1;
        }

        // bias + relu + tf32 round -> Hs
#pragma unroll
        for (int f = 0; f < 2; f++) {
            int col = 16 * wn + 8 * f + 2 * t;
            float bv0 = b1e[c * 64 + col];
            float bv1 = b1e[c * 64 + col + 1];
            float2 lo, hi;
            lo.x = tf32r(fmaxf(c1[f][0] + bv0, 0.f));
            lo.y = tf32r(fmaxf(c1[f][1] + bv1, 0.f));
            hi.x = tf32r(fmaxf(c1[f][2] + bv0, 0.f));
            hi.y = tf32r(fmaxf(c1[f][3] + bv1, 0.f));
            *((float2*)&Hs[rA * HS_STRIDE + col])       = lo;
            *((float2*)&Hs[(rA + 8) * HS_STRIDE + col]) = hi;
        }
        __syncthreads();

        // ================= GEMM2: acc += H @ W2[c*64..+64][:], 4 stages ===
        for (int kb = 0; kb < 4; kb++) {
            if (kb < 3)      stage2(buf ^ 1, c, kb + 1);
            else if (c < 7)  stage1(buf ^ 1, c + 1, 0);
            cp_commit();
            cp_wait1();
            __syncthreads();

            const float* Ws = Wst + buf * STAGE_FLOATS;
#pragma unroll
            for (int ks = 0; ks < 2; ks++) {
                int kc = kb * 16 + ks * 8 + t;
                float a[4];
                a[0] = Hs[rA * HS_STRIDE + kc];
                a[1] = Hs[(rA + 8) * HS_STRIDE + kc];
                a[2] = Hs[rA * HS_STRIDE + kc + 4];
                a[3] = Hs[(rA + 8) * HS_STRIDE + kc + 4];
#pragma unroll
                for (int f = 0; f < 8; f++) {
                    int col = 64 * wn + 8 * f + g;
                    float b0 = Ws[(ks * 8 + t) * W2S_STRIDE + col];
                    float bv = Ws[(ks * 8 + t + 4) * W2S_STRIDE + col];
                    mma_tf32(acc2[f], a, b0, bv);
                }
            }
            __syncthreads();
            buf ^= 1;
        }
    }

    // ---- epilogue: scratch[slot][tok][col] = w * (acc + b2) ----
#pragma unroll
    for (int hrow = 0; hrow < 2; hrow++) {
        int r = rA + 8 * hrow;
        if (r < m) {
            float wgt = s_wt[r];
            float* op = &g_scratch[s_slot[r]][s_tok[r]][0];
#pragma unroll
            for (int f = 0; f < 8; f++) {
                int col = 64 * wn + 8 * f + 2 * t;
                float2 o;
                o.x = wgt * (acc2[f][2 * hrow + 0] + b2e[col]);
                o.y = wgt * (acc2[f][2 * hrow + 1] + b2e[col + 1]);
                *((float2*)(op + col)) = o;
            }
        }
    }
}

// ---------------------------------------------------------------------------
__global__ void combine_kernel(float* __restrict__ out) {
    int idx = blockIdx.x * blockDim.x + threadIdx.x;
    const float4* s0 = (const float4*)g_scratch[0];
    const float4* s1 = (const float4*)g_scratch[1];
    float4 a = s0[idx], b = s1[idx];
    float4 o;
    o.x = a.x + b.x; o.y = a.y + b.y; o.z = a.z + b.z; o.w = a.w + b.w;
    ((float4*)out)[idx] = o;
}

// ---------------------------------------------------------------------------
extern "C" void kernel_launch(void* const* d_in, const int* in_sizes, int n_in,
                              void* d_out, int out_size) {
    const float* x    = (const float*)d_in[0];
    const float* Wg   = (const float*)d_in[1];
    const float* bg   = (const float*)d_in[2];
    const float* bias = (const float*)d_in[3];
    const float* W1   = (const float*)d_in[4];
    const float* b1   = (const float*)d_in[5];
    const float* W2   = (const float*)d_in[6];
    const float* b2   = (const float*)d_in[7];
    float* out = (float*)d_out;

    cudaFuncSetAttribute(expert_kernel,
                         cudaFuncAttributeMaxDynamicSharedMemorySize, SMEM_BYTES);

    zero_kernel<<<1, 32>>>();
    convert_w_kernel<<<2048, 256>>>(W1, W2);
    route_kernel<<<(T_TOKENS * 32) / 256, 256>>>(x, Wg, bg, bias);
    expert_kernel<<<NUM_EXPERTS * MAX_TILES, 256, SMEM_BYTES>>>(x, b1, b2);
    combine_kernel<<<(T_TOKENS * D_MODEL / 4) / 256, 256>>>(out);
}

// round 4
// speedup vs baseline: 2.3891x; 1.2717x over previous
#include <cuda_runtime.h>
#include <math.h>
#include <stdint.h>

#define D_MODEL     256
#define EXPERT_DIM  512
#define NUM_EXPERTS 8
#define T_TOKENS    4096
#define TILE_T      32

#define XS_STRIDE   260
#define HS_STRIDE   68
#define W1S_STRIDE  72
#define W2S_STRIDE  264
#define STAGE_FLOATS 4224            // max(32*72, 16*264)
#define NSLOT        3
#define NSTAGE       96              // 8 chunks * (8 W1 + 4 W2)
#define SMEM_FLOATS  (32*XS_STRIDE + 32*HS_STRIDE + NSLOT*STAGE_FLOATS + 96)
#define SMEM_BYTES   (SMEM_FLOATS * 4)
#define EGRID        296

// ---- device scratch ----
__device__ int   g_cnt[NUM_EXPERTS];
__device__ int   g_tok [NUM_EXPERTS][T_TOKENS];
__device__ float g_wt  [NUM_EXPERTS][T_TOKENS];
__device__ int   g_slot[NUM_EXPERTS][T_TOKENS];
__device__ float g_scratch[2][T_TOKENS][D_MODEL];
__device__ float g_W1c[NUM_EXPERTS * D_MODEL * EXPERT_DIM];
__device__ float g_W2c[NUM_EXPERTS * EXPERT_DIM * D_MODEL];
__device__ int   g_total;
__device__ int2  g_items[1032];      // (expert, start)

// ---------------------------------------------------------------------------
__device__ __forceinline__ float tf32r(float x) {
    uint32_t u;
    asm("cvt.rna.tf32.f32 %0, %1;" : "=r"(u) : "f"(x));
    return __uint_as_float(u);
}

__device__ __forceinline__ void mma_tf32(float c[4], const float a[4],
                                         float b0, float b1) {
    const uint32_t* A = reinterpret_cast<const uint32_t*>(a);
    uint32_t B0 = __float_as_uint(b0), B1 = __float_as_uint(b1);
    asm volatile(
        "mma.sync.aligned.m16n8k8.row.col.f32.tf32.tf32.f32 "
        "{%0,%1,%2,%3}, {%4,%5,%6,%7}, {%8,%9}, {%0,%1,%2,%3};\n"
        : "+f"(c[0]), "+f"(c[1]), "+f"(c[2]), "+f"(c[3])
        : "r"(A[0]), "r"(A[1]), "r"(A[2]), "r"(A[3]), "r"(B0), "r"(B1));
}

__device__ __forceinline__ void cp16(uint32_t dst, const float* src) {
    asm volatile("cp.async.ca.shared.global [%0], [%1], 16;" :: "r"(dst), "l"(src));
}
__device__ __forceinline__ void cp_commit() { asm volatile("cp.async.commit_group;"); }
__device__ __forceinline__ void cp_wait1()  { asm volatile("cp.async.wait_group 1;"); }
__device__ __forceinline__ void cp_wait0()  { asm volatile("cp.async.wait_group 0;"); }

// ---------------------------------------------------------------------------
__global__ void zero_kernel() {
    if (threadIdx.x < NUM_EXPERTS) g_cnt[threadIdx.x] = 0;
}

__global__ void convert_w_kernel(const float* __restrict__ W1,
                                 const float* __restrict__ W2) {
    int j = blockIdx.x * blockDim.x + threadIdx.x;
    const int N4 = NUM_EXPERTS * D_MODEL * EXPERT_DIM / 4;
    float4 v; float4* dst;
    if (j < N4) { v = ((const float4*)W1)[j]; dst = (float4*)g_W1c + j; }
    else        { v = ((const float4*)W2)[j - N4]; dst = (float4*)g_W2c + (j - N4); }
    v.x = tf32r(v.x); v.y = tf32r(v.y); v.z = tf32r(v.z); v.w = tf32r(v.w);
    *dst = v;
}

// ---------------------------------------------------------------------------
__global__ void route_kernel(const float* __restrict__ x,
                             const float* __restrict__ Wg,
                             const float* __restrict__ bg,
                             const float* __restrict__ bias) {
    int warp = (blockIdx.x * blockDim.x + threadIdx.x) >> 5;
    int lane = threadIdx.x & 31;
    if (warp >= T_TOKENS) return;
    int t = warp;

    const float* xr = x + (size_t)t * D_MODEL;
    float acc[NUM_EXPERTS];
#pragma unroll
    for (int e = 0; e < NUM_EXPERTS; e++) acc[e] = 0.f;

#pragma unroll
    for (int j = 0; j < D_MODEL / 32; j++) {
        int k = lane + j * 32;
        float xv = xr[k];
        const float4* wrow = (const float4*)(Wg + (size_t)k * NUM_EXPERTS);
        float4 w0 = wrow[0], w1 = wrow[1];
        acc[0] += xv * w0.x; acc[1] += xv * w0.y;
        acc[2] += xv * w0.z; acc[3] += xv * w0.w;
        acc[4] += xv * w1.x; acc[5] += xv * w1.y;
        acc[6] += xv * w1.z; acc[7] += xv * w1.w;
    }
#pragma unroll
    for (int e = 0; e < NUM_EXPERTS; e++) {
#pragma unroll
        for (int off = 16; off > 0; off >>= 1)
            acc[e] += __shfl_xor_sync(0xffffffffu, acc[e], off);
    }

    if (lane == 0) {
        float best = -INFINITY, second = -INFINITY;
        int b0 = 0, b1 = 0;
#pragma unroll
        for (int e = 0; e < NUM_EXPERTS; e++) {
            float v = acc[e] + bg[e] + bias[e];
            if (v > best)        { second = best; b1 = b0; best = v; b0 = e; }
            else if (v > second) { second = v; b1 = e; }
        }
        float e1  = expf(second - best);
        float inv = 1.f / (1.f + e1);

        int p0 = atomicAdd(&g_cnt[b0], 1);
        g_tok[b0][p0] = t; g_wt[b0][p0] = inv;      g_slot[b0][p0] = 0;
        int p1 = atomicAdd(&g_cnt[b1], 1);
        g_tok[b1][p1] = t; g_wt[b1][p1] = e1 * inv; g_slot[b1][p1] = 1;
    }
}

// ---------------------------------------------------------------------------
// Build compact work queue of (expert, tile_start) items.
__global__ void sched_kernel() {
    __shared__ int off[NUM_EXPERTS + 1];
    int lane = threadIdx.x;
    if (lane == 0) {
        int t = 0;
#pragma unroll
        for (int e = 0; e < NUM_EXPERTS; e++) {
            off[e] = t;
            t += (g_cnt[e] + TILE_T - 1) / TILE_T;
        }
        off[NUM_EXPERTS] = t;
        g_total = t;
    }
    __syncthreads();
#pragma unroll
    for (int e = 0; e < NUM_EXPERTS; e++) {
        int nt = off[e + 1] - off[e];
        for (int i = lane; i < nt; i += 32)
            g_items[off[e] + i] = make_int2(e, i * TILE_T);
    }
}

// ---------------------------------------------------------------------------
// Persistent-ish: 296 blocks, each loops over compacted items.
// 3-slot cp.async ring, flat 96-stage stream, one barrier per stage.
__global__ void __launch_bounds__(256, 2)
expert_kernel(const float* __restrict__ x,
              const float* __restrict__ b1,
              const float* __restrict__ b2) {
    extern __shared__ float sm[];
    float* Xs  = sm;                               // [32][260]
    float* Hs  = sm + 32 * XS_STRIDE;              // [32][68]
    float* Wst = Hs + 32 * HS_STRIDE;              // [3][4224]
    int*   s_tok  = (int*)(Wst + NSLOT * STAGE_FLOATS);
    float* s_wt   = (float*)(s_tok + 32);
    int*   s_slot = (int*)(s_wt + 32);

    int tid  = threadIdx.x;
    int wid  = tid >> 5;
    int wm   = wid >> 2;
    int wn   = wid & 3;
    int lane = tid & 31;
    int g = lane >> 2, t = lane & 3;
    int rA = 16 * wm + g;

    uint32_t wst_sa = (uint32_t)__cvta_generic_to_shared(Wst);
    int total = g_total;

    for (int it = blockIdx.x; it < total; it += EGRID) {
        int2 item = g_items[it];
        int e = item.x, start = item.y;
        int m = min(TILE_T, g_cnt[e] - start);

        const float* W1p = g_W1c + (size_t)e * D_MODEL * EXPERT_DIM;
        const float* W2p = g_W2c + (size_t)e * EXPERT_DIM * D_MODEL;
        const float* b1e = b1 + e * EXPERT_DIM;
        const float* b2e = b2 + e * D_MODEL;

        // stage s: c = s/12, j = s%12. j<8 -> W1 rows 32j..+32 of cols c*64..+64
        //                              j>=8 -> W2 rows c*64+16(j-8)..+16, all 256 cols
        auto issue_stage = [&](int s) {
            int slot = s % NSLOT;
            int c = s / 12, j = s % 12;
            uint32_t base = wst_sa + (uint32_t)(slot * STAGE_FLOATS) * 4u;
            if (j < 8) {
#pragma unroll
                for (int i = 0; i < 2; i++) {
                    int o = tid + 256 * i;
                    int row = o >> 4, q = o & 15;
                    cp16(base + (uint32_t)(row * W1S_STRIDE + q * 4) * 4u,
                         W1p + (size_t)(j * 32 + row) * EXPERT_DIM + c * 64 + q * 4);
                }
            } else {
#pragma unroll
                for (int i = 0; i < 4; i++) {
                    int o = tid + 256 * i;
                    int row = o >> 6, q = o & 63;
                    cp16(base + (uint32_t)(row * W2S_STRIDE + q * 4) * 4u,
                         W2p + (size_t)(c * 64 + (j - 8) * 16 + row) * D_MODEL + q * 4);
                }
            }
        };

        __syncthreads();   // prev item's epilogue done before s_tok overwrite
        if (tid < TILE_T) {
            if (tid < m) {
                s_tok[tid]  = g_tok [e][start + tid];
                s_wt[tid]   = g_wt  [e][start + tid];
                s_slot[tid] = g_slot[e][start + tid];
            } else {
                s_tok[tid] = 0; s_wt[tid] = 0.f; s_slot[tid] = 0;
            }
        }
        issue_stage(0); cp_commit();
        issue_stage(1); cp_commit();
        __syncthreads();   // s_tok visible for gather

        // gather X tile (tf32-rounded)
#pragma unroll
        for (int i = 0; i < 8; i++) {
            int idx = tid + i * 256;
            int row = idx >> 6, q = idx & 63;
            float4 v = make_float4(0.f, 0.f, 0.f, 0.f);
            if (row < m)
                v = ((const float4*)(x + (size_t)s_tok[row] * D_MODEL))[q];
            v.x = tf32r(v.x); v.y = tf32r(v.y); v.z = tf32r(v.z); v.w = tf32r(v.w);
            *((float4*)&Xs[row * XS_STRIDE + q * 4]) = v;
        }

        float acc2[8][4];
#pragma unroll
        for (int f = 0; f < 8; f++)
#pragma unroll
            for (int r = 0; r < 4; r++) acc2[f][r] = 0.f;
        float c1[2][4];

        for (int s = 0; s < NSTAGE; s++) {
            if (s >= NSTAGE - 2) cp_wait0(); else cp_wait1();
            __syncthreads();           // stage s data visible; all warps past s-1
            if (s + 2 < NSTAGE) { issue_stage(s + 2); cp_commit(); }

            int c = s / 12, j = s % 12;
            const float* Ws = Wst + (s % NSLOT) * STAGE_FLOATS;

            if (j < 8) {
                // ---- GEMM1 stage: K rows 32j..+32 ----
                if (j == 0) {
#pragma unroll
                    for (int f = 0; f < 2; f++)
#pragma unroll
                        for (int r = 0; r < 4; r++) c1[f][r] = 0.f;
                }
#pragma unroll
                for (int ks = 0; ks < 4; ks++) {
                    int k0 = j * 32 + ks * 8 + t;
                    float a[4];
                    a[0] = Xs[rA * XS_STRIDE + k0];
                    a[1] = Xs[(rA + 8) * XS_STRIDE + k0];
                    a[2] = Xs[rA * XS_STRIDE + k0 + 4];
                    a[3] = Xs[(rA + 8) * XS_STRIDE + k0 + 4];
#pragma unroll
                    for (int f = 0; f < 2; f++) {
                        int col = 16 * wn + 8 * f + g;
                        float b0 = Ws[(ks * 8 + t) * W1S_STRIDE + col];
                        float bv = Ws[(ks * 8 + t + 4) * W1S_STRIDE + col];
                        mma_tf32(c1[f], a, b0, bv);
                    }
                }
                if (j == 7) {
                    // bias + relu + tf32 round -> Hs (read after next sync)
#pragma unroll
                    for (int f = 0; f < 2; f++) {
                        int col = 16 * wn + 8 * f + 2 * t;
                        float bv0 = b1e[c * 64 + col];
                        float bv1 = b1e[c * 64 + col + 1];
                        float2 lo, hi;
                        lo.x = tf32r(fmaxf(c1[f][0] + bv0, 0.f));
                        lo.y = tf32r(fmaxf(c1[f][1] + bv1, 0.f));
                        hi.x = tf32r(fmaxf(c1[f][2] + bv0, 0.f));
                        hi.y = tf32r(fmaxf(c1[f][3] + bv1, 0.f));
                        *((float2*)&Hs[rA * HS_STRIDE + col])       = lo;
                        *((float2*)&Hs[(rA + 8) * HS_STRIDE + col]) = hi;
                    }
                }
            } else {
                // ---- GEMM2 stage: K rows c*64+16(j-8)..+16 of H chunk ----
#pragma unroll
                for (int ks = 0; ks < 2; ks++) {
                    int kc = (j - 8) * 16 + ks * 8 + t;
                    float a[4];
                    a[0] = Hs[rA * HS_STRIDE + kc];
                    a[1] = Hs[(rA + 8) * HS_STRIDE + kc];
                    a[2] = Hs[rA * HS_STRIDE + kc + 4];
                    a[3] = Hs[(rA + 8) * HS_STRIDE + kc + 4];
#pragma unroll
                    for (int f = 0; f < 8; f++) {
                        int col = 64 * wn + 8 * f + g;
                        float b0 = Ws[(ks * 8 + t) * W2S_STRIDE + col];
                        float bv = Ws[(ks * 8 + t + 4) * W2S_STRIDE + col];
                        mma_tf32(acc2[f], a, b0, bv);
                    }
                }
            }
        }

        // ---- epilogue ----
#pragma unroll
        for (int hrow = 0; hrow < 2; hrow++) {
            int r = rA + 8 * hrow;
            if (r < m) {
                float wgt = s_wt[r];
                float* op = &g_scratch[s_slot[r]][s_tok[r]][0];
#pragma unroll
                for (int f = 0; f < 8; f++) {
                    int col = 64 * wn + 8 * f + 2 * t;
                    float2 o;
                    o.x = wgt * (acc2[f][2 * hrow + 0] + b2e[col]);
                    o.y = wgt * (acc2[f][2 * hrow + 1] + b2e[col + 1]);
                    *((float2*)(op + col)) = o;
                }
            }
        }
    }
}

// ---------------------------------------------------------------------------
__global__ void combine_kernel(float* __restrict__ out) {
    int idx = blockIdx.x * blockDim.x + threadIdx.x;
    const float4* s0 = (const float4*)g_scratch[0];
    const float4* s1 = (const float4*)g_scratch[1];
    float4 a = s0[idx], b = s1[idx];
    float4 o;
    o.x = a.x + b.x; o.y = a.y + b.y; o.z = a.z + b.z; o.w = a.w + b.w;
    ((float4*)out)[idx] = o;
}

// ---------------------------------------------------------------------------
extern "C" void kernel_launch(void* const* d_in, const int* in_sizes, int n_in,
                              void* d_out, int out_size) {
    const float* x    = (const float*)d_in[0];
    const float* Wg   = (const float*)d_in[1];
    const float* bg   = (const float*)d_in[2];
    const float* bias = (const float*)d_in[3];
    const float* W1   = (const float*)d_in[4];
    const float* b1   = (const float*)d_in[5];
    const float* W2   = (const float*)d_in[6];
    const float* b2   = (const float*)d_in[7];
    float* out = (float*)d_out;

    cudaFuncSetAttribute(expert_kernel,
                         cudaFuncAttributeMaxDynamicSharedMemorySize, SMEM_BYTES);

    zero_kernel<<<1, 32>>>();
    convert_w_kernel<<<2048, 256>>>(W1, W2);
    route_kernel<<<(T_TOKENS * 32) / 256, 256>>>(x, Wg, bg, bias);
    sched_kernel<<<1, 32>>>();
    expert_kernel<<<EGRID, 256, SMEM_BYTES>>>(x, b1, b2);
    combine_kernel<<<(T_TOKENS * D_MODEL / 4) / 256, 256>>>(out);
}

// round 5
// speedup vs baseline: 2.8628x; 1.1983x over previous
#include <cuda_runtime.h>
#include <math.h>
#include <stdint.h>

#define D_MODEL     256
#define EXPERT_DIM  512
#define NUM_EXPERTS 8
#define T_TOKENS    4096
#define TILE_T      64

#define XS_STRIDE   260
#define HS_STRIDE   68
#define W1S_STRIDE  72
#define W2S_STRIDE  264
#define STAGE_FLOATS 4224            // max(32*72, 16*264)
#define NSLOT        3
#define NSTAGE       96              // 8 chunks * (8 W1 + 4 W2)
#define SMEM_FLOATS  (TILE_T*XS_STRIDE + TILE_T*HS_STRIDE + NSLOT*STAGE_FLOATS + 224)
#define SMEM_BYTES   (SMEM_FLOATS * 4)
#define EGRID        148

// ---- device scratch ----
__device__ int   g_cnt[NUM_EXPERTS];
__device__ int   g_tok [NUM_EXPERTS][T_TOKENS];
__device__ float g_wt  [NUM_EXPERTS][T_TOKENS];
__device__ int   g_slot[NUM_EXPERTS][T_TOKENS];
__device__ float g_scratch[2][T_TOKENS][D_MODEL];
__device__ float g_W1c[NUM_EXPERTS * D_MODEL * EXPERT_DIM];
__device__ float g_W2c[NUM_EXPERTS * EXPERT_DIM * D_MODEL];

// ---------------------------------------------------------------------------
__device__ __forceinline__ float tf32r(float x) {
    uint32_t u;
    asm("cvt.rna.tf32.f32 %0, %1;" : "=r"(u) : "f"(x));
    return __uint_as_float(u);
}

__device__ __forceinline__ void mma_tf32(float c[4], const float a[4],
                                         float b0, float b1) {
    const uint32_t* A = reinterpret_cast<const uint32_t*>(a);
    uint32_t B0 = __float_as_uint(b0), B1 = __float_as_uint(b1);
    asm volatile(
        "mma.sync.aligned.m16n8k8.row.col.f32.tf32.tf32.f32 "
        "{%0,%1,%2,%3}, {%4,%5,%6,%7}, {%8,%9}, {%0,%1,%2,%3};\n"
        : "+f"(c[0]), "+f"(c[1]), "+f"(c[2]), "+f"(c[3])
        : "r"(A[0]), "r"(A[1]), "r"(A[2]), "r"(A[3]), "r"(B0), "r"(B1));
}

__device__ __forceinline__ void cp16(uint32_t dst, const float* src) {
    asm volatile("cp.async.ca.shared.global [%0], [%1], 16;" :: "r"(dst), "l"(src));
}
__device__ __forceinline__ void cp_commit() { asm volatile("cp.async.commit_group;"); }
__device__ __forceinline__ void cp_wait1()  { asm volatile("cp.async.wait_group 1;"); }
__device__ __forceinline__ void cp_wait0()  { asm volatile("cp.async.wait_group 0;"); }

// ---------------------------------------------------------------------------
// Convert weights to tf32; also zero routing counters (block 0).
__global__ void convert_w_kernel(const float* __restrict__ W1,
                                 const float* __restrict__ W2) {
    if (blockIdx.x == 0 && threadIdx.x < NUM_EXPERTS) g_cnt[threadIdx.x] = 0;
    int j = blockIdx.x * blockDim.x + threadIdx.x;
    const int N4 = NUM_EXPERTS * D_MODEL * EXPERT_DIM / 4;
    float4 v; float4* dst;
    if (j < N4) { v = ((const float4*)W1)[j]; dst = (float4*)g_W1c + j; }
    else        { v = ((const float4*)W2)[j - N4]; dst = (float4*)g_W2c + (j - N4); }
    v.x = tf32r(v.x); v.y = tf32r(v.y); v.z = tf32r(v.z); v.w = tf32r(v.w);
    *dst = v;
}

// ---------------------------------------------------------------------------
__global__ void route_kernel(const float* __restrict__ x,
                             const float* __restrict__ Wg,
                             const float* __restrict__ bg,
                             const float* __restrict__ bias) {
    int warp = (blockIdx.x * blockDim.x + threadIdx.x) >> 5;
    int lane = threadIdx.x & 31;
    if (warp >= T_TOKENS) return;
    int t = warp;

    const float* xr = x + (size_t)t * D_MODEL;
    float acc[NUM_EXPERTS];
#pragma unroll
    for (int e = 0; e < NUM_EXPERTS; e++) acc[e] = 0.f;

#pragma unroll
    for (int j = 0; j < D_MODEL / 32; j++) {
        int k = lane + j * 32;
        float xv = xr[k];
        const float4* wrow = (const float4*)(Wg + (size_t)k * NUM_EXPERTS);
        float4 w0 = wrow[0], w1 = wrow[1];
        acc[0] += xv * w0.x; acc[1] += xv * w0.y;
        acc[2] += xv * w0.z; acc[3] += xv * w0.w;
        acc[4] += xv * w1.x; acc[5] += xv * w1.y;
        acc[6] += xv * w1.z; acc[7] += xv * w1.w;
    }
#pragma unroll
    for (int e = 0; e < NUM_EXPERTS; e++) {
#pragma unroll
        for (int off = 16; off > 0; off >>= 1)
            acc[e] += __shfl_xor_sync(0xffffffffu, acc[e], off);
    }

    if (lane == 0) {
        float best = -INFINITY, second = -INFINITY;
        int b0 = 0, b1 = 0;
#pragma unroll
        for (int e = 0; e < NUM_EXPERTS; e++) {
            float v = acc[e] + bg[e] + bias[e];
            if (v > best)        { second = best; b1 = b0; best = v; b0 = e; }
            else if (v > second) { second = v; b1 = e; }
        }
        float e1  = expf(second - best);
        float inv = 1.f / (1.f + e1);

        int p0 = atomicAdd(&g_cnt[b0], 1);
        g_tok[b0][p0] = t; g_wt[b0][p0] = inv;      g_slot[b0][p0] = 0;
        int p1 = atomicAdd(&g_cnt[b1], 1);
        g_tok[b1][p1] = t; g_wt[b1][p1] = e1 * inv; g_slot[b1][p1] = 1;
    }
}

// ---------------------------------------------------------------------------
// 148 blocks, one 64-token item each (<=136 items total). 8 warps = 2m x 4n.
// Flat 96-stage cp.async ring, one barrier per stage.
__global__ void __launch_bounds__(256, 1)
expert_kernel(const float* __restrict__ x,
              const float* __restrict__ b1,
              const float* __restrict__ b2) {
    extern __shared__ float sm[];
    float* Xs  = sm;                                  // [64][260]
    float* Hs  = sm + TILE_T * XS_STRIDE;             // [64][68]
    float* Wst = Hs + TILE_T * HS_STRIDE;             // [3][4224]
    int*   s_tok  = (int*)(Wst + NSLOT * STAGE_FLOATS);
    float* s_wt   = (float*)(s_tok + TILE_T);
    int*   s_slot = (int*)(s_wt + TILE_T);

    int tid  = threadIdx.x;
    int wid  = tid >> 5;
    int wm   = wid >> 2;        // 0..1 -> rows 32*wm .. +32
    int wn   = wid & 3;
    int lane = tid & 31;
    int g = lane >> 2, t = lane & 3;
    int rA = 32 * wm + g;

    // inline scheduler: flat item id -> (expert, start)
    int cnt[NUM_EXPERTS], off[NUM_EXPERTS + 1];
    off[0] = 0;
#pragma unroll
    for (int e = 0; e < NUM_EXPERTS; e++) {
        cnt[e] = g_cnt[e];
        off[e + 1] = off[e] + (cnt[e] + TILE_T - 1) / TILE_T;
    }
    int total = off[NUM_EXPERTS];

    uint32_t wst_sa = (uint32_t)__cvta_generic_to_shared(Wst);

    for (int it = blockIdx.x; it < total; it += EGRID) {
        int e = 0;
#pragma unroll
        for (int k = 1; k < NUM_EXPERTS; k++)
            if (it >= off[k]) e = k;
        int start = (it - off[e]) * TILE_T;
        int m = min(TILE_T, cnt[e] - start);

        const float* W1p = g_W1c + (size_t)e * D_MODEL * EXPERT_DIM;
        const float* W2p = g_W2c + (size_t)e * EXPERT_DIM * D_MODEL;
        const float* b1e = b1 + e * EXPERT_DIM;
        const float* b2e = b2 + e * D_MODEL;

        auto issue_stage = [&](int s) {
            int slot = s % NSLOT;
            int c = s / 12, j = s % 12;
            uint32_t base = wst_sa + (uint32_t)(slot * STAGE_FLOATS) * 4u;
            if (j < 8) {
#pragma unroll
                for (int i = 0; i < 2; i++) {
                    int o = tid + 256 * i;
                    int row = o >> 4, q = o & 15;
                    cp16(base + (uint32_t)(row * W1S_STRIDE + q * 4) * 4u,
                         W1p + (size_t)(j * 32 + row) * EXPERT_DIM + c * 64 + q * 4);
                }
            } else {
#pragma unroll
                for (int i = 0; i < 4; i++) {
                    int o = tid + 256 * i;
                    int row = o >> 6, q = o & 63;
                    cp16(base + (uint32_t)(row * W2S_STRIDE + q * 4) * 4u,
                         W2p + (size_t)(c * 64 + (j - 8) * 16 + row) * D_MODEL + q * 4);
                }
            }
        };

        __syncthreads();
        if (tid < TILE_T) {
            if (tid < m) {
                s_tok[tid]  = g_tok [e][start + tid];
                s_wt[tid]   = g_wt  [e][start + tid];
                s_slot[tid] = g_slot[e][start + tid];
            } else {
                s_tok[tid] = 0; s_wt[tid] = 0.f; s_slot[tid] = 0;
            }
        }
        issue_stage(0); cp_commit();
        issue_stage(1); cp_commit();
        __syncthreads();

        // gather X tile (tf32-rounded): 64 rows x 64 float4 = 4096
#pragma unroll
        for (int i = 0; i < 16; i++) {
            int idx = tid + i * 256;
            int row = idx >> 6, q = idx & 63;
            float4 v = make_float4(0.f, 0.f, 0.f, 0.f);
            if (row < m)
                v = ((const float4*)(x + (size_t)s_tok[row] * D_MODEL))[q];
            v.x = tf32r(v.x); v.y = tf32r(v.y); v.z = tf32r(v.z); v.w = tf32r(v.w);
            *((float4*)&Xs[row * XS_STRIDE + q * 4]) = v;
        }

        float acc2[2][8][4];
#pragma unroll
        for (int mt = 0; mt < 2; mt++)
#pragma unroll
            for (int f = 0; f < 8; f++)
#pragma unroll
                for (int r = 0; r < 4; r++) acc2[mt][f][r] = 0.f;
        float c1[2][2][4];

        for (int s = 0; s < NSTAGE; s++) {
            if (s >= NSTAGE - 2) cp_wait0(); else cp_wait1();
            __syncthreads();
            if (s + 2 < NSTAGE) { issue_stage(s + 2); cp_commit(); }

            int c = s / 12, j = s % 12;
            const float* Ws = Wst + (s % NSLOT) * STAGE_FLOATS;

            if (j < 8) {
                if (j == 0) {
#pragma unroll
                    for (int mt = 0; mt < 2; mt++)
#pragma unroll
                        for (int f = 0; f < 2; f++)
#pragma unroll
                            for (int r = 0; r < 4; r++) c1[mt][f][r] = 0.f;
                }
#pragma unroll
                for (int ks = 0; ks < 4; ks++) {
                    int k0 = j * 32 + ks * 8 + t;
                    float a[2][4];
#pragma unroll
                    for (int mt = 0; mt < 2; mt++) {
                        int r0 = rA + 16 * mt;
                        a[mt][0] = Xs[r0 * XS_STRIDE + k0];
                        a[mt][1] = Xs[(r0 + 8) * XS_STRIDE + k0];
                        a[mt][2] = Xs[r0 * XS_STRIDE + k0 + 4];
                        a[mt][3] = Xs[(r0 + 8) * XS_STRIDE + k0 + 4];
                    }
#pragma unroll
                    for (int f = 0; f < 2; f++) {
                        int col = 16 * wn + 8 * f + g;
                        float b0 = Ws[(ks * 8 + t) * W1S_STRIDE + col];
                        float bv = Ws[(ks * 8 + t + 4) * W1S_STRIDE + col];
                        mma_tf32(c1[0][f], a[0], b0, bv);
                        mma_tf32(c1[1][f], a[1], b0, bv);
                    }
                }
                if (j == 7) {
#pragma unroll
                    for (int mt = 0; mt < 2; mt++) {
#pragma unroll
                        for (int f = 0; f < 2; f++) {
                            int col = 16 * wn + 8 * f + 2 * t;
                            float bv0 = b1e[c * 64 + col];
                            float bv1 = b1e[c * 64 + col + 1];
                            int r0 = rA + 16 * mt;
                            float2 lo, hi;
                            lo.x = tf32r(fmaxf(c1[mt][f][0] + bv0, 0.f));
                            lo.y = tf32r(fmaxf(c1[mt][f][1] + bv1, 0.f));
                            hi.x = tf32r(fmaxf(c1[mt][f][2] + bv0, 0.f));
                            hi.y = tf32r(fmaxf(c1[mt][f][3] + bv1, 0.f));
                            *((float2*)&Hs[r0 * HS_STRIDE + col])       = lo;
                            *((float2*)&Hs[(r0 + 8) * HS_STRIDE + col]) = hi;
                        }
                    }
                }
            } else {
#pragma unroll
                for (int ks = 0; ks < 2; ks++) {
                    int kc = (j - 8) * 16 + ks * 8 + t;
                    float a[2][4];
#pragma unroll
                    for (int mt = 0; mt < 2; mt++) {
                        int r0 = rA + 16 * mt;
                        a[mt][0] = Hs[r0 * HS_STRIDE + kc];
                        a[mt][1] = Hs[(r0 + 8) * HS_STRIDE + kc];
                        a[mt][2] = Hs[r0 * HS_STRIDE + kc + 4];
                        a[mt][3] = Hs[(r0 + 8) * HS_STRIDE + kc + 4];
                    }
#pragma unroll
                    for (int f = 0; f < 8; f++) {
                        int col = 64 * wn + 8 * f + g;
                        float b0 = Ws[(ks * 8 + t) * W2S_STRIDE + col];
                        float bv = Ws[(ks * 8 + t + 4) * W2S_STRIDE + col];
                        mma_tf32(acc2[0][f], a[0], b0, bv);
                        mma_tf32(acc2[1][f], a[1], b0, bv);
                    }
                }
            }
        }

        // ---- epilogue ----
#pragma unroll
        for (int mt = 0; mt < 2; mt++) {
#pragma unroll
            for (int hrow = 0; hrow < 2; hrow++) {
                int r = rA + 16 * mt + 8 * hrow;
                if (r < m) {
                    float wgt = s_wt[r];
                    float* op = &g_scratch[s_slot[r]][s_tok[r]][0];
#pragma unroll
                    for (int f = 0; f < 8; f++) {
                        int col = 64 * wn + 8 * f + 2 * t;
                        float2 o;
                        o.x = wgt * (acc2[mt][f][2 * hrow + 0] + b2e[col]);
                        o.y = wgt * (acc2[mt][f][2 * hrow + 1] + b2e[col + 1]);
                        *((float2*)(op + col)) = o;
                    }
                }
            }
        }
    }
}

// ---------------------------------------------------------------------------
__global__ void combine_kernel(float* __restrict__ out) {
    int idx = blockIdx.x * blockDim.x + threadIdx.x;
    const float4* s0 = (const float4*)g_scratch[0];
    const float4* s1 = (const float4*)g_scratch[1];
    float4 a = s0[idx], b = s1[idx];
    float4 o;
    o.x = a.x + b.x; o.y = a.y + b.y; o.z = a.z + b.z; o.w = a.w + b.w;
    ((float4*)out)[idx] = o;
}

// ---------------------------------------------------------------------------
extern "C" void kernel_launch(void* const* d_in, const int* in_sizes, int n_in,
                              void* d_out, int out_size) {
    const float* x    = (const float*)d_in[0];
    const float* Wg   = (const float*)d_in[1];
    const float* bg   = (const float*)d_in[2];
    const float* bias = (const float*)d_in[3];
    const float* W1   = (const float*)d_in[4];
    const float* b1   = (const float*)d_in[5];
    const float* W2   = (const float*)d_in[6];
    const float* b2   = (const float*)d_in[7];
    float* out = (float*)d_out;

    cudaFuncSetAttribute(expert_kernel,
                         cudaFuncAttributeMaxDynamicSharedMemorySize, SMEM_BYTES);

    convert_w_kernel<<<2048, 256>>>(W1, W2);
    route_kernel<<<(T_TOKENS * 32) / 256, 256>>>(x, Wg, bg, bias);
    expert_kernel<<<EGRID, 256, SMEM_BYTES>>>(x, b1, b2);
    combine_kernel<<<(T_TOKENS * D_MODEL / 4) / 256, 256>>>(out);
}

// round 6
// speedup vs baseline: 2.9477x; 1.0297x over previous
#include <cuda_runtime.h>
#include <math.h>
#include <stdint.h>

#define D_MODEL     256
#define EXPERT_DIM  512
#define NUM_EXPERTS 8
#define T_TOKENS    4096
#define TILE_T      64
#define EGRID       148

#define XS_ROW      264          // floats per row (132 float2, 132%16==4 -> LDS.64 conflict-free)
#define HS_ROW      72           // 36 float2, 36%16==4
#define STAGE_FLOATS 8192        // W2 stage: 4 k8 * 256 n * 4 t * 2
#define NSLOT       3
#define NSTAGE      48           // 8 chunks * (4 W1 + 2 W2)
#define SMEM_FLOATS (TILE_T*XS_ROW + TILE_T*HS_ROW + NSLOT*STAGE_FLOATS + 256)
#define SMEM_BYTES  (SMEM_FLOATS * 4)

// ---- device scratch ----
__device__ int   g_cnt[NUM_EXPERTS];
__device__ int   g_tok [NUM_EXPERTS][T_TOKENS];
__device__ float g_wt  [NUM_EXPERTS][T_TOKENS];
__device__ int   g_slot[NUM_EXPERTS][T_TOKENS];
__device__ float g_scratch[2][T_TOKENS][D_MODEL];
// pair-packed tf32 weights: [e][k8][n][t] float2 = (W[k8*8+t][n], W[k8*8+t+4][n])
__device__ float g_W1pk[NUM_EXPERTS * D_MODEL * EXPERT_DIM];   // k8:32, n:512
__device__ float g_W2pk[NUM_EXPERTS * EXPERT_DIM * D_MODEL];   // k8:64, n:256
__device__ int   g_done;
__device__ int   g_done2;

// ---------------------------------------------------------------------------
__device__ __forceinline__ float tf32r(float x) {
    uint32_t u;
    asm("cvt.rna.tf32.f32 %0, %1;" : "=r"(u) : "f"(x));
    return __uint_as_float(u);
}

__device__ __forceinline__ void mma_tf32(float c[4], const float a[4],
                                         float b0, float b1) {
    const uint32_t* A = reinterpret_cast<const uint32_t*>(a);
    uint32_t B0 = __float_as_uint(b0), B1 = __float_as_uint(b1);
    asm volatile(
        "mma.sync.aligned.m16n8k8.row.col.f32.tf32.tf32.f32 "
        "{%0,%1,%2,%3}, {%4,%5,%6,%7}, {%8,%9}, {%0,%1,%2,%3};\n"
        : "+f"(c[0]), "+f"(c[1]), "+f"(c[2]), "+f"(c[3])
        : "r"(A[0]), "r"(A[1]), "r"(A[2]), "r"(A[3]), "r"(B0), "r"(B1));
}

__device__ __forceinline__ void cp16(uint32_t dst, const float* src) {
    asm volatile("cp.async.ca.shared.global [%0], [%1], 16;" :: "r"(dst), "l"(src));
}
__device__ __forceinline__ void cp_commit() { asm volatile("cp.async.commit_group;"); }
__device__ __forceinline__ void cp_wait1()  { asm volatile("cp.async.wait_group 1;"); }
__device__ __forceinline__ void cp_wait0()  { asm volatile("cp.async.wait_group 0;"); }

// ---------------------------------------------------------------------------
// Fused init: blocks [0,512) route tokens; blocks [512,4608) pair-pack weights.
__global__ void init_kernel(const float* __restrict__ x,
                            const float* __restrict__ Wg,
                            const float* __restrict__ bg,
                            const float* __restrict__ bias,
                            const float* __restrict__ W1,
                            const float* __restrict__ W2) {
    int bid = blockIdx.x;
    int tid = threadIdx.x;

    if (bid < 512) {
        // ---------------- routing: one warp per token ----------------
        int warp = (bid * 256 + tid) >> 5;
        int lane = tid & 31;
        int t = warp;

        const float* xr = x + (size_t)t * D_MODEL;
        float acc[NUM_EXPERTS];
#pragma unroll
        for (int e = 0; e < NUM_EXPERTS; e++) acc[e] = 0.f;
#pragma unroll
        for (int j = 0; j < D_MODEL / 32; j++) {
            int k = lane + j * 32;
            float xv = xr[k];
            const float4* wrow = (const float4*)(Wg + (size_t)k * NUM_EXPERTS);
            float4 w0 = wrow[0], w1 = wrow[1];
            acc[0] += xv * w0.x; acc[1] += xv * w0.y;
            acc[2] += xv * w0.z; acc[3] += xv * w0.w;
            acc[4] += xv * w1.x; acc[5] += xv * w1.y;
            acc[6] += xv * w1.z; acc[7] += xv * w1.w;
        }
#pragma unroll
        for (int e = 0; e < NUM_EXPERTS; e++) {
#pragma unroll
            for (int off = 16; off > 0; off >>= 1)
                acc[e] += __shfl_xor_sync(0xffffffffu, acc[e], off);
        }
        if (lane == 0) {
            float best = -INFINITY, second = -INFINITY;
            int b0 = 0, b1 = 0;
#pragma unroll
            for (int e = 0; e < NUM_EXPERTS; e++) {
                float v = acc[e] + bg[e] + bias[e];
                if (v > best)        { second = best; b1 = b0; best = v; b0 = e; }
                else if (v > second) { second = v; b1 = e; }
            }
            float e1  = expf(second - best);
            float inv = 1.f / (1.f + e1);
            int p0 = atomicAdd(&g_cnt[b0], 1);
            g_tok[b0][p0] = t; g_wt[b0][p0] = inv;      g_slot[b0][p0] = 0;
            int p1 = atomicAdd(&g_cnt[b1], 1);
            g_tok[b1][p1] = t; g_wt[b1][p1] = e1 * inv; g_slot[b1][p1] = 1;
        }
    } else {
        // ---------------- weight pair-packing (tf32-rounded) ----------
        long j = (long)(bid - 512) * 256 + tid;      // 0 .. 1048575
        if (j < 524288) {
            int n   = (int)(j & 511);
            int r   = (int)(j >> 9);
            int t   = r & 3;
            int ek8 = r >> 2;
            int k8  = ek8 & 31;
            int e   = ek8 >> 5;
            const float* src = W1 + ((size_t)e * D_MODEL + k8 * 8 + t) * EXPERT_DIM + n;
            float2 v;
            v.x = tf32r(src[0]);
            v.y = tf32r(src[4 * EXPERT_DIM]);
            *((float2*)&g_W1pk[(((size_t)(e * 32 + k8) * 512 + n) * 4 + t) * 2]) = v;
        } else {
            long jj = j - 524288;
            int n   = (int)(jj & 255);
            int r   = (int)(jj >> 8);
            int t   = r & 3;
            int ek8 = r >> 2;
            int k8  = ek8 & 63;
            int e   = ek8 >> 6;
            const float* src = W2 + ((size_t)e * EXPERT_DIM + k8 * 8 + t) * D_MODEL + n;
            float2 v;
            v.x = tf32r(src[0]);
            v.y = tf32r(src[4 * D_MODEL]);
            *((float2*)&g_W2pk[(((size_t)(e * 64 + k8) * 256 + n) * 4 + t) * 2]) = v;
        }
    }
}

// ---------------------------------------------------------------------------
// 148 blocks; <=136 items of 64 tokens -> single wave. 8 warps = 2m x 4n.
// 48-stage cp.async ring (3 slots), LDS.64 fragment loads, fused combine tail.
__global__ void __launch_bounds__(256, 1)
expert_kernel(const float* __restrict__ x,
              const float* __restrict__ b1,
              const float* __restrict__ b2,
              float* __restrict__ out) {
    extern __shared__ float sm[];
    float* Xs  = sm;                                  // [64][264] pair-packed
    float* Hs  = sm + TILE_T * XS_ROW;                // [64][72]  pair-packed
    float* Wst = Hs + TILE_T * HS_ROW;                // [3][8192]
    int*   s_tok  = (int*)(Wst + NSLOT * STAGE_FLOATS);
    float* s_wt   = (float*)(s_tok + TILE_T);
    int*   s_slot = (int*)(s_wt + TILE_T);

    int tid  = threadIdx.x;
    int wid  = tid >> 5;
    int wm   = wid >> 2;        // 0..1 -> rows 32*wm..+32
    int wn   = wid & 3;         // 0..3
    int lane = tid & 31;
    int g = lane >> 2, t = lane & 3;
    int rA = 32 * wm + g;

    // inline scheduler
    int cnt[NUM_EXPERTS], off[NUM_EXPERTS + 1];
    off[0] = 0;
#pragma unroll
    for (int e = 0; e < NUM_EXPERTS; e++) {
        cnt[e] = g_cnt[e];
        off[e + 1] = off[e] + (cnt[e] + TILE_T - 1) / TILE_T;
    }
    int total = off[NUM_EXPERTS];

    uint32_t wst_sa = (uint32_t)__cvta_generic_to_shared(Wst);

    for (int it = blockIdx.x; it < total; it += EGRID) {
        int e = 0;
#pragma unroll
        for (int k = 1; k < NUM_EXPERTS; k++)
            if (it >= off[k]) e = k;
        int start = (it - off[e]) * TILE_T;
        int m = min(TILE_T, cnt[e] - start);

        const float* W1p = g_W1pk + (size_t)e * D_MODEL * EXPERT_DIM;
        const float* W2p = g_W2pk + (size_t)e * EXPERT_DIM * D_MODEL;
        const float* b1e = b1 + e * EXPERT_DIM;
        const float* b2e = b2 + e * D_MODEL;

        // stage s: c = s/6, j = s%6.
        //  j<4  : W1 K-rows [j*64 .. +64) (k8 j*8..+8), cols c*64..+64
        //  j>=4 : W2 H-rows (k8 = c*8 + (j-4)*4 .. +4), all 256 cols
        auto issue_stage = [&](int s) {
            int slot = s % NSLOT;
            int c = s / 6, j = s % 6;
            uint32_t base = wst_sa + (uint32_t)(slot * STAGE_FLOATS) * 4u;
            if (j < 4) {
#pragma unroll
                for (int i = 0; i < 4; i++) {
                    int o = tid + 256 * i;           // 1024 cp16
                    int l = o >> 7, w = o & 127;
                    cp16(base + (uint32_t)(l * 512 + w * 4) * 4u,
                         W1p + ((size_t)(j * 8 + l) * 512 + c * 64) * 8 + w * 4);
                }
            } else {
                int k80 = c * 8 + (j - 4) * 4;
#pragma unroll
                for (int i = 0; i < 8; i++) {
                    int o = tid + 256 * i;           // 2048 cp16
                    int l = o >> 9, w = o & 511;
                    cp16(base + (uint32_t)(l * 2048 + w * 4) * 4u,
                         W2p + (size_t)(k80 + l) * 2048 + w * 4);
                }
            }
        };

        __syncthreads();
        if (tid < TILE_T) {
            if (tid < m) {
                s_tok[tid]  = g_tok [e][start + tid];
                s_wt[tid]   = g_wt  [e][start + tid];
                s_slot[tid] = g_slot[e][start + tid];
            } else {
                s_tok[tid] = 0; s_wt[tid] = 0.f; s_slot[tid] = 0;
            }
        }
        issue_stage(0); cp_commit();
        issue_stage(1); cp_commit();
        __syncthreads();

        // gather X tile into pair-packed layout (tf32-rounded)
#pragma unroll
        for (int i = 0; i < 16; i++) {
            int idx = tid + i * 256;
            int row = idx >> 6, q = idx & 63;
            float4 v = make_float4(0.f, 0.f, 0.f, 0.f);
            if (row < m)
                v = ((const float4*)(x + (size_t)s_tok[row] * D_MODEL))[q];
            float vv[4] = { tf32r(v.x), tf32r(v.y), tf32r(v.z), tf32r(v.w) };
#pragma unroll
            for (int ii = 0; ii < 4; ii++) {
                int col = 4 * q + ii;
                int k8 = col >> 3, p = col & 7;
                Xs[row * XS_ROW + k8 * 8 + (p & 3) * 2 + (p >> 2)] = vv[ii];
            }
        }

        float acc2[2][8][4];
#pragma unroll
        for (int mt = 0; mt < 2; mt++)
#pragma unroll
            for (int f = 0; f < 8; f++)
#pragma unroll
                for (int r = 0; r < 4; r++) acc2[mt][f][r] = 0.f;
        float c1[2][2][4];

        for (int s = 0; s < NSTAGE; s++) {
            if (s >= NSTAGE - 2) cp_wait0(); else cp_wait1();
            __syncthreads();
            if (s + 2 < NSTAGE) { issue_stage(s + 2); cp_commit(); }

            int c = s / 6, j = s % 6;
            const float* Ws = Wst + (s % NSLOT) * STAGE_FLOATS;

            if (j < 4) {
                if (j == 0) {
#pragma unroll
                    for (int mt = 0; mt < 2; mt++)
#pragma unroll
                        for (int f = 0; f < 2; f++)
#pragma unroll
                            for (int r = 0; r < 4; r++) c1[mt][f][r] = 0.f;
                }
#pragma unroll
                for (int ks = 0; ks < 8; ks++) {
                    int k8 = j * 8 + ks;
                    float a[2][4];
#pragma unroll
                    for (int mt = 0; mt < 2; mt++) {
                        int r0 = rA + 16 * mt;
                        float2 lo = *((const float2*)&Xs[r0 * XS_ROW + k8 * 8 + 2 * t]);
                        float2 hi = *((const float2*)&Xs[(r0 + 8) * XS_ROW + k8 * 8 + 2 * t]);
                        a[mt][0] = lo.x; a[mt][1] = hi.x;
                        a[mt][2] = lo.y; a[mt][3] = hi.y;
                    }
#pragma unroll
                    for (int f = 0; f < 2; f++) {
                        int col = 16 * wn + 8 * f + g;
                        float2 b = *((const float2*)&Ws[((ks * 64 + col) * 4 + t) * 2]);
                        mma_tf32(c1[0][f], a[0], b.x, b.y);
                        mma_tf32(c1[1][f], a[1], b.x, b.y);
                    }
                }
                if (j == 3) {
                    // bias + relu + tf32 round -> pair-packed Hs
#pragma unroll
                    for (int mt = 0; mt < 2; mt++) {
#pragma unroll
                        for (int f = 0; f < 2; f++) {
                            int col0 = 16 * wn + 8 * f + 2 * t;   // within-chunk col
                            float bv0 = b1e[c * 64 + col0];
                            float bv1 = b1e[c * 64 + col0 + 1];
                            int k8h = 2 * wn + f;
                            int p0 = 2 * t, p1 = 2 * t + 1;
                            int o0 = k8h * 8 + (p0 & 3) * 2 + (p0 >> 2);
                            int o1 = k8h * 8 + (p1 & 3) * 2 + (p1 >> 2);
                            int r0 = rA + 16 * mt;
                            Hs[r0 * HS_ROW + o0]       = tf32r(fmaxf(c1[mt][f][0] + bv0, 0.f));
                            Hs[r0 * HS_ROW + o1]       = tf32r(fmaxf(c1[mt][f][1] + bv1, 0.f));
                            Hs[(r0 + 8) * HS_ROW + o0] = tf32r(fmaxf(c1[mt][f][2] + bv0, 0.f));
                            Hs[(r0 + 8) * HS_ROW + o1] = tf32r(fmaxf(c1[mt][f][3] + bv1, 0.f));
                        }
                    }
                }
            } else {
#pragma unroll
                for (int ks = 0; ks < 4; ks++) {
                    int k8h = (j - 4) * 4 + ks;       // 0..7 within chunk
                    float a[2][4];
#pragma unroll
                    for (int mt = 0; mt < 2; mt++) {
                        int r0 = rA + 16 * mt;
                        float2 lo = *((const float2*)&Hs[r0 * HS_ROW + k8h * 8 + 2 * t]);
                        float2 hi = *((const float2*)&Hs[(r0 + 8) * HS_ROW + k8h * 8 + 2 * t]);
                        a[mt][0] = lo.x; a[mt][1] = hi.x;
                        a[mt][2] = lo.y; a[mt][3] = hi.y;
                    }
#pragma unroll
                    for (int f = 0; f < 8; f++) {
                        int col = 64 * wn + 8 * f + g;
                        float2 b = *((const float2*)&Ws[((ks * 256 + col) * 4 + t) * 2]);
                        mma_tf32(acc2[0][f], a[0], b.x, b.y);
                        mma_tf32(acc2[1][f], a[1], b.x, b.y);
                    }
                }
            }
        }

        // ---- epilogue: scratch[slot][tok][col] = w * (acc + b2) ----
#pragma unroll
        for (int mt = 0; mt < 2; mt++) {
#pragma unroll
            for (int hrow = 0; hrow < 2; hrow++) {
                int r = rA + 16 * mt + 8 * hrow;
                if (r < m) {
                    float wgt = s_wt[r];
                    float* op = &g_scratch[s_slot[r]][s_tok[r]][0];
#pragma unroll
                    for (int f = 0; f < 8; f++) {
                        int col = 64 * wn + 8 * f + 2 * t;
                        float2 o;
                        o.x = wgt * (acc2[mt][f][2 * hrow + 0] + b2e[col]);
                        o.y = wgt * (acc2[mt][f][2 * hrow + 1] + b2e[col + 1]);
                        *((float2*)(op + col)) = o;
                    }
                }
            }
        }
    }

    // ================= fused combine: wait for all blocks =================
    __threadfence();
    __syncthreads();
    if (tid == 0) {
        atomicAdd(&g_done, 1);
        while (*((volatile int*)&g_done) < EGRID) { }
    }
    __syncthreads();
    __threadfence();

    const float4* s0 = (const float4*)g_scratch[0];
    const float4* s1 = (const float4*)g_scratch[1];
    float4* o4 = (float4*)out;
    const int N4 = T_TOKENS * D_MODEL / 4;
    for (int i = blockIdx.x * 256 + tid; i < N4; i += EGRID * 256) {
        float4 a = s0[i], b = s1[i];
        float4 o;
        o.x = a.x + b.x; o.y = a.y + b.y; o.z = a.z + b.z; o.w = a.w + b.w;
        o4[i] = o;
    }

    // ---- last block resets counters for the next graph replay ----
    __threadfence();
    __syncthreads();
    if (tid == 0) {
        int v = atomicAdd(&g_done2, 1);
        if (v == EGRID - 1) {
            g_done = 0; g_done2 = 0;
#pragma unroll
            for (int e = 0; e < NUM_EXPERTS; e++) g_cnt[e] = 0;
        }
    }
}

// ---------------------------------------------------------------------------
extern "C" void kernel_launch(void* const* d_in, const int* in_sizes, int n_in,
                              void* d_out, int out_size) {
    const float* x    = (const float*)d_in[0];
    const float* Wg   = (const float*)d_in[1];
    const float* bg   = (const float*)d_in[2];
    const float* bias = (const float*)d_in[3];
    const float* W1   = (const float*)d_in[4];
    const float* b1   = (const float*)d_in[5];
    const float* W2   = (const float*)d_in[6];
    const float* b2   = (const float*)d_in[7];
    float* out = (float*)d_out;

    cudaFuncSetAttribute(expert_kernel,
                         cudaFuncAttributeMaxDynamicSharedMemorySize, SMEM_BYTES);

    init_kernel<<<4608, 256>>>(x, Wg, bg, bias, W1, W2);
    expert_kernel<<<EGRID, 256, SMEM_BYTES>>>(x, b1, b2, out);
}